// round 11
// baseline (speedup 1.0000x reference)
#include <cuda_runtime.h>
#include <cuda_fp16.h>

#define DIM 128
#define NN 200000
#define NE 12800000
#define SCAN_B 1024
#define NBLK 196            // 196*1024 = 200704 >= NN
#define NBINS 512
#define RPB 391             // rows per bin; 512*391 = 200192 >= NN

// Static device scratch (no cudaMalloc allowed).
__device__ float    g_side[(size_t)NN * DIM];   // 102.4 MB result of SpMM
__device__ __half   g_ego_h[(size_t)NN * DIM];  // 51.2 MB fp16 gather copy
__device__ unsigned g_pay[NE];                  // 51.2 MB packed (col<<14 | q14)
__device__ uint2    g_stage[NE];                // 102.4 MB bin-partitioned staging
__device__ int      g_cnt[NBLK * SCAN_B];       // histogram (zeroed by scan_fused)
__device__ int      g_woff[NN];                 // running offsets for phase B
__device__ int      g_boff[NBINS];              // running offsets for phase A
__device__ int      g_rowptr[NN + 1];
__device__ int      g_bsum[NBLK];
__device__ int      g_flag;                     // grid barrier counter

// ---------------------------------------------------------------------------
// packed fp32x2 helpers (FFMA2 — only reachable via PTX fma.rn.f32x2)
// ---------------------------------------------------------------------------
__device__ __forceinline__ unsigned long long pack2(float x) {
    unsigned long long r;
    asm("mov.b64 %0, {%1, %2};" : "=l"(r) : "f"(x), "f"(x));
    return r;
}
__device__ __forceinline__ void fma2(unsigned long long& d,
                                     unsigned long long a,
                                     unsigned long long b) {
    asm("fma.rn.f32x2 %0, %1, %2, %0;" : "+l"(d) : "l"(a), "l"(b));
}

// ---------------------------------------------------------------------------
// 1) prep (fp16 shadow of ego) + hist (row degree) + flag reset
// ---------------------------------------------------------------------------
__global__ void prephist_kernel(const float* __restrict__ ego,
                                const int* __restrict__ erow) {
    if (blockIdx.x == 0 && threadIdx.x == 0) g_flag = 0;
    size_t nthr = (size_t)gridDim.x * blockDim.x;
    size_t tid0 = (size_t)blockIdx.x * blockDim.x + threadIdx.x;
    size_t total = (size_t)NN * DIM / 8;
    for (size_t i = tid0; i < total; i += nthr) {
        float4 a = __ldg((const float4*)ego + 2 * i);
        float4 b = __ldg((const float4*)ego + 2 * i + 1);
        __half2 h[4];
        h[0] = __floats2half2_rn(a.x, a.y);
        h[1] = __floats2half2_rn(a.z, a.w);
        h[2] = __floats2half2_rn(b.x, b.y);
        h[3] = __floats2half2_rn(b.z, b.w);
        *((uint4*)g_ego_h + i) = *(uint4*)h;
    }
    for (size_t i = tid0; i < NE / 4; i += nthr) {
        int4 r = __ldg((const int4*)erow + i);
        atomicAdd(&g_cnt[r.x], 1);
        atomicAdd(&g_cnt[r.y], 1);
        atomicAdd(&g_cnt[r.z], 1);
        atomicAdd(&g_cnt[r.w], 1);
    }
}

// ---------------------------------------------------------------------------
// 2) single-kernel exclusive scan with grid-wide software barrier.
//    Also zeroes g_cnt and seeds g_woff / g_boff for this replay.
// ---------------------------------------------------------------------------
__global__ void scan_fused() {
    __shared__ int sh[SCAN_B];
    __shared__ int sb[256];
    int t = threadIdx.x;
    int b = blockIdx.x;
    int gid = b * SCAN_B + t;

    int v = g_cnt[gid];
    g_cnt[gid] = 0;                         // reset for next replay
    sh[t] = v;
    __syncthreads();
    for (int off = 1; off < SCAN_B; off <<= 1) {
        int u = (t >= off) ? sh[t - off] : 0;
        __syncthreads();
        sh[t] += u;
        __syncthreads();
    }
    int excl = sh[t] - v;

    if (t == SCAN_B - 1) {
        g_bsum[b] = sh[t];                  // block total
        __threadfence();
        atomicAdd(&g_flag, 1);
    }
    if (t == 0) {
        while (*(volatile int*)&g_flag < NBLK) { }
    }
    __syncthreads();

    if (t < 256) sb[t] = (t < NBLK) ? *(volatile int*)&g_bsum[t] : 0;
    __syncthreads();
    for (int off = 1; off < 256; off <<= 1) {
        int u = (t < 256 && t >= off) ? sb[t - off] : 0;
        __syncthreads();
        if (t < 256) sb[t] += u;
        __syncthreads();
    }
    int boff = (b == 0) ? 0 : sb[b - 1];

    int val = excl + boff;
    if (gid < NN) {
        g_rowptr[gid] = val;
        g_woff[gid] = val;
        if (gid % RPB == 0) g_boff[gid / RPB] = val;   // bin cursors (free)
    }
    if (b == 0 && t == 0) g_rowptr[NN] = NE;
}

// ---------------------------------------------------------------------------
// 3) scatter phase A: partition edges into 512 row-range bins.
//    Sequential per-bin cursor grants -> consecutive 8B writes -> sectors
//    fill while L2-resident (no write amplification).
// ---------------------------------------------------------------------------
__global__ void binA_kernel(const int* __restrict__ erow,
                            const int* __restrict__ ecol,
                            const float* __restrict__ eval) {
    int i0 = blockIdx.x * blockDim.x + threadIdx.x;
    int stride = gridDim.x * blockDim.x;
    for (int i = i0; i < NE / 4; i += stride) {
        int4   r = __ldg((const int4*)erow + i);
        int4   c = __ldg((const int4*)ecol + i);
        float4 v = __ldg((const float4*)eval + i);
        int p0 = atomicAdd(&g_boff[r.x / RPB], 1);
        int p1 = atomicAdd(&g_boff[r.y / RPB], 1);
        int p2 = atomicAdd(&g_boff[r.z / RPB], 1);
        int p3 = atomicAdd(&g_boff[r.w / RPB], 1);
        unsigned q0 = min(16383u, (unsigned)__float2int_rn(v.x * 16384.f));
        unsigned q1 = min(16383u, (unsigned)__float2int_rn(v.y * 16384.f));
        unsigned q2 = min(16383u, (unsigned)__float2int_rn(v.z * 16384.f));
        unsigned q3 = min(16383u, (unsigned)__float2int_rn(v.w * 16384.f));
        g_stage[p0] = make_uint2(((unsigned)c.x << 14) | q0, (unsigned)r.x);
        g_stage[p1] = make_uint2(((unsigned)c.y << 14) | q1, (unsigned)r.y);
        g_stage[p2] = make_uint2(((unsigned)c.z << 14) | q2, (unsigned)r.z);
        g_stage[p3] = make_uint2(((unsigned)c.w << 14) | q3, (unsigned)r.w);
    }
}

// ---------------------------------------------------------------------------
// 4) scatter phase B: one CTA per bin. Final payload window (~100KB) and
//    row cursors (~1.6KB) are L2-local -> sectors fill completely.
// ---------------------------------------------------------------------------
__global__ __launch_bounds__(512)
void binB_kernel() {
    int b = blockIdx.x;
    int s = g_rowptr[b * RPB];
    int hi = (b + 1) * RPB; if (hi > NN) hi = NN;
    int e = g_rowptr[hi];
    int i = s + threadIdx.x;
    // unroll 2 for MLP
    for (; i + 512 < e; i += 1024) {
        uint2 rec0 = g_stage[i];
        uint2 rec1 = g_stage[i + 512];
        int p0 = atomicAdd(&g_woff[rec0.y], 1);
        int p1 = atomicAdd(&g_woff[rec1.y], 1);
        g_pay[p0] = rec0.x;
        g_pay[p1] = rec1.x;
    }
    for (; i < e; i += 512) {
        uint2 rec = g_stage[i];
        int p = atomicAdd(&g_woff[rec.y], 1);
        g_pay[p] = rec.x;
    }
}

// ---------------------------------------------------------------------------
// 5) CSR SpMM: one warp per row, 16 lanes x uint4 per edge row,
//    2 edges processed concurrently (lane groups), 4 loads in flight/group.
// ---------------------------------------------------------------------------
__global__ __launch_bounds__(512)
void spmm_csr_kernel() {
    int lane = threadIdx.x & 31;
    int g    = lane >> 4;        // edge-parity group (0/1)
    int l16  = lane & 15;        // covers dims [l16*8, l16*8+8)
    int row = (blockIdx.x * blockDim.x + threadIdx.x) >> 5;
    if (row >= NN) return;

    int start = g_rowptr[row];
    int end   = g_rowptr[row + 1];

    float4 accA = make_float4(0.f, 0.f, 0.f, 0.f);
    float4 accB = make_float4(0.f, 0.f, 0.f, 0.f);
    const float INV = 1.f / 16384.f;

    for (int e0 = start; e0 < end; e0 += 32) {
        int idx = e0 + lane;
        unsigned pay = (idx < end) ? __ldg(g_pay + idx) : 0u;
        int cnt = min(32, end - e0);
        int j = 0;
        #pragma unroll 1
        for (; j + 8 <= cnt; j += 8) {
            unsigned pj[4];
            uint4 raw[4];
            #pragma unroll
            for (int u = 0; u < 4; u++)
                pj[u] = __shfl_sync(0xffffffffu, pay, j + 2 * u + g);
            #pragma unroll
            for (int u = 0; u < 4; u++)
                raw[u] = __ldg((const uint4*)(g_ego_h + (size_t)(pj[u] >> 14) * DIM) + l16);
            #pragma unroll
            for (int u = 0; u < 4; u++) {
                float v = (float)(pj[u] & 0x3FFFu) * INV;
                float2 f0 = __half22float2(*(__half2*)&raw[u].x);
                float2 f1 = __half22float2(*(__half2*)&raw[u].y);
                float2 f2 = __half22float2(*(__half2*)&raw[u].z);
                float2 f3 = __half22float2(*(__half2*)&raw[u].w);
                accA.x = fmaf(f0.x, v, accA.x);
                accA.y = fmaf(f0.y, v, accA.y);
                accA.z = fmaf(f1.x, v, accA.z);
                accA.w = fmaf(f1.y, v, accA.w);
                accB.x = fmaf(f2.x, v, accB.x);
                accB.y = fmaf(f2.y, v, accB.y);
                accB.z = fmaf(f3.x, v, accB.z);
                accB.w = fmaf(f3.y, v, accB.w);
            }
        }
        #pragma unroll 1
        for (; j < cnt; j += 2) {
            int src = j + g;
            bool valid = src < cnt;
            unsigned p = __shfl_sync(0xffffffffu, pay, valid ? src : (cnt - 1));
            if (valid) {
                float v = (float)(p & 0x3FFFu) * INV;
                uint4 raw = __ldg((const uint4*)(g_ego_h + (size_t)(p >> 14) * DIM) + l16);
                float2 f0 = __half22float2(*(__half2*)&raw.x);
                float2 f1 = __half22float2(*(__half2*)&raw.y);
                float2 f2 = __half22float2(*(__half2*)&raw.z);
                float2 f3 = __half22float2(*(__half2*)&raw.w);
                accA.x = fmaf(f0.x, v, accA.x);
                accA.y = fmaf(f0.y, v, accA.y);
                accA.z = fmaf(f1.x, v, accA.z);
                accA.w = fmaf(f1.y, v, accA.w);
                accB.x = fmaf(f2.x, v, accB.x);
                accB.y = fmaf(f2.y, v, accB.y);
                accB.z = fmaf(f3.x, v, accB.z);
                accB.w = fmaf(f3.y, v, accB.w);
            }
        }
    }

    accA.x += __shfl_xor_sync(0xffffffffu, accA.x, 16);
    accA.y += __shfl_xor_sync(0xffffffffu, accA.y, 16);
    accA.z += __shfl_xor_sync(0xffffffffu, accA.z, 16);
    accA.w += __shfl_xor_sync(0xffffffffu, accA.w, 16);
    accB.x += __shfl_xor_sync(0xffffffffu, accB.x, 16);
    accB.y += __shfl_xor_sync(0xffffffffu, accB.y, 16);
    accB.z += __shfl_xor_sync(0xffffffffu, accB.z, 16);
    accB.w += __shfl_xor_sync(0xffffffffu, accB.w, 16);

    if (g == 0) {
        float4* dst = (float4*)(g_side + (size_t)row * DIM + l16 * 8);
        dst[0] = accA;
        dst[1] = accB;
    }
}

// ---------------------------------------------------------------------------
// 6) fused bi-interaction (fp32, packed f32x2 FMA).
// ---------------------------------------------------------------------------
#define MT 64
#define APAD 132

__global__ __launch_bounds__(256, 1)
void fused_kernel(const float* __restrict__ ego,
                  const float* __restrict__ W1, const float* __restrict__ b1,
                  const float* __restrict__ W2, const float* __restrict__ b2,
                  float* __restrict__ out) {
    extern __shared__ float sh[];
    float* sW1 = sh;
    float* sW2 = sh + DIM * DIM;
    float* sA  = sh + 2 * DIM * DIM;
    float* sP  = sA + MT * APAD;

    int tid = threadIdx.x;

    for (int i = tid; i < DIM * DIM / 4; i += 256) {
        ((float4*)sW1)[i] = __ldg((const float4*)W1 + i);
        ((float4*)sW2)[i] = __ldg((const float4*)W2 + i);
    }

    int m0 = blockIdx.x * MT;
    for (int i = tid; i < MT * (DIM / 4); i += 256) {
        int mm = i >> 5;
        int kk = i & 31;
        float4 e = __ldg((const float4*)(ego + (size_t)(m0 + mm) * DIM) + kk);
        float4 s = *((const float4*)(g_side + (size_t)(m0 + mm) * DIM) + kk);
        float* a = sA + mm * APAD + kk * 4;
        float* p = sP + mm * APAD + kk * 4;
        a[0] = e.x + s.x; a[1] = e.y + s.y; a[2] = e.z + s.z; a[3] = e.w + s.w;
        p[0] = e.x * s.x; p[1] = e.y * s.y; p[2] = e.z * s.z; p[3] = e.w * s.w;
    }
    __syncthreads();

    int nb = (tid & 15) * 8;
    int mb = (tid >> 4) * 4;

    unsigned long long acc1[4][4], acc2[4][4];
    #pragma unroll
    for (int i = 0; i < 4; i++)
        #pragma unroll
        for (int j = 0; j < 4; j++) { acc1[i][j] = 0ULL; acc2[i][j] = 0ULL; }

    #pragma unroll 4
    for (int k = 0; k < DIM; k++) {
        ulonglong2 w1a = *(ulonglong2*)&sW1[k * DIM + nb];
        ulonglong2 w1b = *(ulonglong2*)&sW1[k * DIM + nb + 4];
        ulonglong2 w2a = *(ulonglong2*)&sW2[k * DIM + nb];
        ulonglong2 w2b = *(ulonglong2*)&sW2[k * DIM + nb + 4];
        #pragma unroll
        for (int i = 0; i < 4; i++) {
            unsigned long long ad = pack2(sA[(mb + i) * APAD + k]);
            unsigned long long pd = pack2(sP[(mb + i) * APAD + k]);
            fma2(acc1[i][0], ad, w1a.x);
            fma2(acc1[i][1], ad, w1a.y);
            fma2(acc1[i][2], ad, w1b.x);
            fma2(acc1[i][3], ad, w1b.y);
            fma2(acc2[i][0], pd, w2a.x);
            fma2(acc2[i][1], pd, w2a.y);
            fma2(acc2[i][2], pd, w2b.x);
            fma2(acc2[i][3], pd, w2b.y);
        }
    }

    #pragma unroll
    for (int i = 0; i < 4; i++) {
        int m = m0 + mb + i;
        #pragma unroll
        for (int jp = 0; jp < 4; jp++) {
            float2 s1 = *(float2*)&acc1[i][jp];
            float2 s2 = *(float2*)&acc2[i][jp];
            int n = nb + jp * 2;
            float x1 = s1.x + __ldg(b1 + n);
            float y1 = s1.y + __ldg(b1 + n + 1);
            float x2 = s2.x + __ldg(b2 + n);
            float y2 = s2.y + __ldg(b2 + n + 1);
            float r1 = (x1 > 0.f ? x1 : 0.01f * x1) + (x2 > 0.f ? x2 : 0.01f * x2);
            float r2 = (y1 > 0.f ? y1 : 0.01f * y1) + (y2 > 0.f ? y2 : 0.01f * y2);
            out[(size_t)m * DIM + n]     = r1;
            out[(size_t)m * DIM + n + 1] = r2;
        }
    }
}

// ---------------------------------------------------------------------------
extern "C" void kernel_launch(void* const* d_in, const int* in_sizes, int n_in,
                              void* d_out, int out_size) {
    const int*   erow = (const int*)d_in[0];
    const int*   ecol = (const int*)d_in[1];
    const float* eval = (const float*)d_in[2];
    const float* ego  = (const float*)d_in[3];
    const float* W1   = (const float*)d_in[4];
    const float* b1   = (const float*)d_in[5];
    const float* W2   = (const float*)d_in[6];
    const float* b2   = (const float*)d_in[7];
    float* out = (float*)d_out;

    const int smem_bytes = (2 * DIM * DIM + 2 * MT * APAD) * (int)sizeof(float);
    cudaFuncSetAttribute(fused_kernel,
                         cudaFuncAttributeMaxDynamicSharedMemorySize, smem_bytes);

    prephist_kernel<<<2048, 256>>>(ego, erow);             // launch 1
    scan_fused<<<NBLK, SCAN_B>>>();                        // launch 2
    binA_kernel<<<2048, 256>>>(erow, ecol, eval);          // launch 3
    binB_kernel<<<NBINS, 512>>>();                         // launch 4 (profiled)
    spmm_csr_kernel<<<(NN * 32 + 511) / 512, 512>>>();     // launch 5
    fused_kernel<<<NN / MT, 256, smem_bytes>>>(ego, W1, b1, W2, b2, out);
}

// round 12
// speedup vs baseline: 2.4491x; 2.4491x over previous
#include <cuda_runtime.h>
#include <cuda_fp16.h>

#define DIM 128
#define NN 200000
#define NE 12800000
#define SCAN_B 1024
#define NBLK 196            // 196*1024 = 200704 >= NN
#define NPASS 2
#define ROWS_PER_PASS 100000

// Static device scratch (no cudaMalloc allowed).
__device__ float    g_side[(size_t)NN * DIM];   // 102.4 MB result of SpMM
__device__ __half   g_ego_h[(size_t)NN * DIM];  // 51.2 MB fp16 gather copy
__device__ unsigned g_pay[NE];                  // 51.2 MB packed (col<<14 | q14)
__device__ int      g_cnt[NBLK * SCAN_B];       // histogram (zeroed by scan_fused)
__device__ int      g_woff[NN];                 // running offsets for scatter
__device__ int      g_rowptr[NN + 1];
__device__ int      g_bsum[NBLK];
__device__ int      g_flag;                     // grid barrier counter

// ---------------------------------------------------------------------------
// packed fp32x2 helpers (FFMA2 — only reachable via PTX fma.rn.f32x2)
// ---------------------------------------------------------------------------
__device__ __forceinline__ unsigned long long pack2(float x) {
    unsigned long long r;
    asm("mov.b64 %0, {%1, %2};" : "=l"(r) : "f"(x), "f"(x));
    return r;
}
__device__ __forceinline__ void fma2(unsigned long long& d,
                                     unsigned long long a,
                                     unsigned long long b) {
    asm("fma.rn.f32x2 %0, %1, %2, %0;" : "+l"(d) : "l"(a), "l"(b));
}

// ---------------------------------------------------------------------------
// 1) prep (fp16 shadow of ego) + hist (row degree) + flag reset
// ---------------------------------------------------------------------------
__global__ void prephist_kernel(const float* __restrict__ ego,
                                const int* __restrict__ erow) {
    if (blockIdx.x == 0 && threadIdx.x == 0) g_flag = 0;
    size_t nthr = (size_t)gridDim.x * blockDim.x;
    size_t tid0 = (size_t)blockIdx.x * blockDim.x + threadIdx.x;
    size_t total = (size_t)NN * DIM / 8;
    for (size_t i = tid0; i < total; i += nthr) {
        float4 a = __ldg((const float4*)ego + 2 * i);
        float4 b = __ldg((const float4*)ego + 2 * i + 1);
        __half2 h[4];
        h[0] = __floats2half2_rn(a.x, a.y);
        h[1] = __floats2half2_rn(a.z, a.w);
        h[2] = __floats2half2_rn(b.x, b.y);
        h[3] = __floats2half2_rn(b.z, b.w);
        *((uint4*)g_ego_h + i) = *(uint4*)h;
    }
    for (size_t i = tid0; i < NE / 4; i += nthr) {
        int4 r = __ldg((const int4*)erow + i);
        atomicAdd(&g_cnt[r.x], 1);
        atomicAdd(&g_cnt[r.y], 1);
        atomicAdd(&g_cnt[r.z], 1);
        atomicAdd(&g_cnt[r.w], 1);
    }
}

// ---------------------------------------------------------------------------
// 2) single-kernel exclusive scan with grid-wide software barrier.
//    Also zeroes g_cnt and seeds g_woff for this replay.
// ---------------------------------------------------------------------------
__global__ void scan_fused() {
    __shared__ int sh[SCAN_B];
    __shared__ int sb[256];
    int t = threadIdx.x;
    int b = blockIdx.x;
    int gid = b * SCAN_B + t;

    int v = g_cnt[gid];
    g_cnt[gid] = 0;                         // reset for next replay
    sh[t] = v;
    __syncthreads();
    for (int off = 1; off < SCAN_B; off <<= 1) {
        int u = (t >= off) ? sh[t - off] : 0;
        __syncthreads();
        sh[t] += u;
        __syncthreads();
    }
    int excl = sh[t] - v;

    if (t == SCAN_B - 1) {
        g_bsum[b] = sh[t];                  // block total
        __threadfence();
        atomicAdd(&g_flag, 1);
    }
    if (t == 0) {
        while (*(volatile int*)&g_flag < NBLK) { }
    }
    __syncthreads();

    if (t < 256) sb[t] = (t < NBLK) ? *(volatile int*)&g_bsum[t] : 0;
    __syncthreads();
    for (int off = 1; off < 256; off <<= 1) {
        int u = (t < 256 && t >= off) ? sb[t - off] : 0;
        __syncthreads();
        if (t < 256) sb[t] += u;
        __syncthreads();
    }
    int boff = (b == 0) ? 0 : sb[b - 1];

    int val = excl + boff;
    if (gid < NN) {
        g_rowptr[gid] = val;
        g_woff[gid] = val;
    }
    if (b == 0 && t == 0) g_rowptr[NN] = NE;
}

// ---------------------------------------------------------------------------
// 3+4) windowed scatter: pass p commits only rows in
//      [p*ROWS_PER_PASS, (p+1)*ROWS_PER_PASS). Write window ~25.6 MB
//      stays L2-resident -> no sector write amplification.
//      Atomics stay spread over 200K counters (no contention).
// ---------------------------------------------------------------------------
__global__ void scatter_kernel(const int* __restrict__ erow,
                               const int* __restrict__ ecol,
                               const float* __restrict__ eval,
                               int lo, int hi) {
    int i0 = blockIdx.x * blockDim.x + threadIdx.x;
    int stride = gridDim.x * blockDim.x;
    for (int i = i0; i < NE / 4; i += stride) {
        int4   r = __ldg((const int4*)erow + i);
        int4   c = __ldg((const int4*)ecol + i);
        float4 v = __ldg((const float4*)eval + i);
        if (r.x >= lo && r.x < hi) {
            int p = atomicAdd(&g_woff[r.x], 1);
            unsigned q = min(16383u, (unsigned)__float2int_rn(v.x * 16384.f));
            g_pay[p] = ((unsigned)c.x << 14) | q;
        }
        if (r.y >= lo && r.y < hi) {
            int p = atomicAdd(&g_woff[r.y], 1);
            unsigned q = min(16383u, (unsigned)__float2int_rn(v.y * 16384.f));
            g_pay[p] = ((unsigned)c.y << 14) | q;
        }
        if (r.z >= lo && r.z < hi) {
            int p = atomicAdd(&g_woff[r.z], 1);
            unsigned q = min(16383u, (unsigned)__float2int_rn(v.z * 16384.f));
            g_pay[p] = ((unsigned)c.z << 14) | q;
        }
        if (r.w >= lo && r.w < hi) {
            int p = atomicAdd(&g_woff[r.w], 1);
            unsigned q = min(16383u, (unsigned)__float2int_rn(v.w * 16384.f));
            g_pay[p] = ((unsigned)c.w << 14) | q;
        }
    }
}

// ---------------------------------------------------------------------------
// 5) CSR SpMM: one warp per row, 16 lanes x uint4 per edge row,
//    2 edges processed concurrently (lane groups), 4 loads in flight/group.
// ---------------------------------------------------------------------------
__global__ __launch_bounds__(512)
void spmm_csr_kernel() {
    int lane = threadIdx.x & 31;
    int g    = lane >> 4;        // edge-parity group (0/1)
    int l16  = lane & 15;        // covers dims [l16*8, l16*8+8)
    int row = (blockIdx.x * blockDim.x + threadIdx.x) >> 5;
    if (row >= NN) return;

    int start = g_rowptr[row];
    int end   = g_rowptr[row + 1];

    float4 accA = make_float4(0.f, 0.f, 0.f, 0.f);
    float4 accB = make_float4(0.f, 0.f, 0.f, 0.f);
    const float INV = 1.f / 16384.f;

    for (int e0 = start; e0 < end; e0 += 32) {
        int idx = e0 + lane;
        unsigned pay = (idx < end) ? __ldg(g_pay + idx) : 0u;
        int cnt = min(32, end - e0);
        int j = 0;
        #pragma unroll 1
        for (; j + 8 <= cnt; j += 8) {
            unsigned pj[4];
            uint4 raw[4];
            #pragma unroll
            for (int u = 0; u < 4; u++)
                pj[u] = __shfl_sync(0xffffffffu, pay, j + 2 * u + g);
            #pragma unroll
            for (int u = 0; u < 4; u++)
                raw[u] = __ldg((const uint4*)(g_ego_h + (size_t)(pj[u] >> 14) * DIM) + l16);
            #pragma unroll
            for (int u = 0; u < 4; u++) {
                float v = (float)(pj[u] & 0x3FFFu) * INV;
                float2 f0 = __half22float2(*(__half2*)&raw[u].x);
                float2 f1 = __half22float2(*(__half2*)&raw[u].y);
                float2 f2 = __half22float2(*(__half2*)&raw[u].z);
                float2 f3 = __half22float2(*(__half2*)&raw[u].w);
                accA.x = fmaf(f0.x, v, accA.x);
                accA.y = fmaf(f0.y, v, accA.y);
                accA.z = fmaf(f1.x, v, accA.z);
                accA.w = fmaf(f1.y, v, accA.w);
                accB.x = fmaf(f2.x, v, accB.x);
                accB.y = fmaf(f2.y, v, accB.y);
                accB.z = fmaf(f3.x, v, accB.z);
                accB.w = fmaf(f3.y, v, accB.w);
            }
        }
        #pragma unroll 1
        for (; j < cnt; j += 2) {
            int src = j + g;
            bool valid = src < cnt;
            unsigned p = __shfl_sync(0xffffffffu, pay, valid ? src : (cnt - 1));
            if (valid) {
                float v = (float)(p & 0x3FFFu) * INV;
                uint4 raw = __ldg((const uint4*)(g_ego_h + (size_t)(p >> 14) * DIM) + l16);
                float2 f0 = __half22float2(*(__half2*)&raw.x);
                float2 f1 = __half22float2(*(__half2*)&raw.y);
                float2 f2 = __half22float2(*(__half2*)&raw.z);
                float2 f3 = __half22float2(*(__half2*)&raw.w);
                accA.x = fmaf(f0.x, v, accA.x);
                accA.y = fmaf(f0.y, v, accA.y);
                accA.z = fmaf(f1.x, v, accA.z);
                accA.w = fmaf(f1.y, v, accA.w);
                accB.x = fmaf(f2.x, v, accB.x);
                accB.y = fmaf(f2.y, v, accB.y);
                accB.z = fmaf(f3.x, v, accB.z);
                accB.w = fmaf(f3.y, v, accB.w);
            }
        }
    }

    accA.x += __shfl_xor_sync(0xffffffffu, accA.x, 16);
    accA.y += __shfl_xor_sync(0xffffffffu, accA.y, 16);
    accA.z += __shfl_xor_sync(0xffffffffu, accA.z, 16);
    accA.w += __shfl_xor_sync(0xffffffffu, accA.w, 16);
    accB.x += __shfl_xor_sync(0xffffffffu, accB.x, 16);
    accB.y += __shfl_xor_sync(0xffffffffu, accB.y, 16);
    accB.z += __shfl_xor_sync(0xffffffffu, accB.z, 16);
    accB.w += __shfl_xor_sync(0xffffffffu, accB.w, 16);

    if (g == 0) {
        float4* dst = (float4*)(g_side + (size_t)row * DIM + l16 * 8);
        dst[0] = accA;
        dst[1] = accB;
    }
}

// ---------------------------------------------------------------------------
// 6) fused bi-interaction (fp32, packed f32x2 FMA).
// ---------------------------------------------------------------------------
#define MT 64
#define APAD 132

__global__ __launch_bounds__(256, 1)
void fused_kernel(const float* __restrict__ ego,
                  const float* __restrict__ W1, const float* __restrict__ b1,
                  const float* __restrict__ W2, const float* __restrict__ b2,
                  float* __restrict__ out) {
    extern __shared__ float sh[];
    float* sW1 = sh;
    float* sW2 = sh + DIM * DIM;
    float* sA  = sh + 2 * DIM * DIM;
    float* sP  = sA + MT * APAD;

    int tid = threadIdx.x;

    for (int i = tid; i < DIM * DIM / 4; i += 256) {
        ((float4*)sW1)[i] = __ldg((const float4*)W1 + i);
        ((float4*)sW2)[i] = __ldg((const float4*)W2 + i);
    }

    int m0 = blockIdx.x * MT;
    for (int i = tid; i < MT * (DIM / 4); i += 256) {
        int mm = i >> 5;
        int kk = i & 31;
        float4 e = __ldg((const float4*)(ego + (size_t)(m0 + mm) * DIM) + kk);
        float4 s = *((const float4*)(g_side + (size_t)(m0 + mm) * DIM) + kk);
        float* a = sA + mm * APAD + kk * 4;
        float* p = sP + mm * APAD + kk * 4;
        a[0] = e.x + s.x; a[1] = e.y + s.y; a[2] = e.z + s.z; a[3] = e.w + s.w;
        p[0] = e.x * s.x; p[1] = e.y * s.y; p[2] = e.z * s.z; p[3] = e.w * s.w;
    }
    __syncthreads();

    int nb = (tid & 15) * 8;
    int mb = (tid >> 4) * 4;

    unsigned long long acc1[4][4], acc2[4][4];
    #pragma unroll
    for (int i = 0; i < 4; i++)
        #pragma unroll
        for (int j = 0; j < 4; j++) { acc1[i][j] = 0ULL; acc2[i][j] = 0ULL; }

    #pragma unroll 4
    for (int k = 0; k < DIM; k++) {
        ulonglong2 w1a = *(ulonglong2*)&sW1[k * DIM + nb];
        ulonglong2 w1b = *(ulonglong2*)&sW1[k * DIM + nb + 4];
        ulonglong2 w2a = *(ulonglong2*)&sW2[k * DIM + nb];
        ulonglong2 w2b = *(ulonglong2*)&sW2[k * DIM + nb + 4];
        #pragma unroll
        for (int i = 0; i < 4; i++) {
            unsigned long long ad = pack2(sA[(mb + i) * APAD + k]);
            unsigned long long pd = pack2(sP[(mb + i) * APAD + k]);
            fma2(acc1[i][0], ad, w1a.x);
            fma2(acc1[i][1], ad, w1a.y);
            fma2(acc1[i][2], ad, w1b.x);
            fma2(acc1[i][3], ad, w1b.y);
            fma2(acc2[i][0], pd, w2a.x);
            fma2(acc2[i][1], pd, w2a.y);
            fma2(acc2[i][2], pd, w2b.x);
            fma2(acc2[i][3], pd, w2b.y);
        }
    }

    #pragma unroll
    for (int i = 0; i < 4; i++) {
        int m = m0 + mb + i;
        #pragma unroll
        for (int jp = 0; jp < 4; jp++) {
            float2 s1 = *(float2*)&acc1[i][jp];
            float2 s2 = *(float2*)&acc2[i][jp];
            int n = nb + jp * 2;
            float x1 = s1.x + __ldg(b1 + n);
            float y1 = s1.y + __ldg(b1 + n + 1);
            float x2 = s2.x + __ldg(b2 + n);
            float y2 = s2.y + __ldg(b2 + n + 1);
            float r1 = (x1 > 0.f ? x1 : 0.01f * x1) + (x2 > 0.f ? x2 : 0.01f * x2);
            float r2 = (y1 > 0.f ? y1 : 0.01f * y1) + (y2 > 0.f ? y2 : 0.01f * y2);
            out[(size_t)m * DIM + n]     = r1;
            out[(size_t)m * DIM + n + 1] = r2;
        }
    }
}

// ---------------------------------------------------------------------------
extern "C" void kernel_launch(void* const* d_in, const int* in_sizes, int n_in,
                              void* d_out, int out_size) {
    const int*   erow = (const int*)d_in[0];
    const int*   ecol = (const int*)d_in[1];
    const float* eval = (const float*)d_in[2];
    const float* ego  = (const float*)d_in[3];
    const float* W1   = (const float*)d_in[4];
    const float* b1   = (const float*)d_in[5];
    const float* W2   = (const float*)d_in[6];
    const float* b2   = (const float*)d_in[7];
    float* out = (float*)d_out;

    const int smem_bytes = (2 * DIM * DIM + 2 * MT * APAD) * (int)sizeof(float);
    cudaFuncSetAttribute(fused_kernel,
                         cudaFuncAttributeMaxDynamicSharedMemorySize, smem_bytes);

    prephist_kernel<<<2048, 256>>>(ego, erow);                      // launch 1
    scan_fused<<<NBLK, SCAN_B>>>();                                 // launch 2
    scatter_kernel<<<2048, 256>>>(erow, ecol, eval, 0,
                                  ROWS_PER_PASS);                   // launch 3
    scatter_kernel<<<2048, 256>>>(erow, ecol, eval, ROWS_PER_PASS,
                                  NN);                              // launch 4 (profiled)
    spmm_csr_kernel<<<(NN * 32 + 511) / 512, 512>>>();              // launch 5
    fused_kernel<<<NN / MT, 256, smem_bytes>>>(ego, W1, b1, W2, b2, out);
}

// round 15
// speedup vs baseline: 3.3705x; 1.3762x over previous
#include <cuda_runtime.h>
#include <cuda_fp16.h>
#include <cstdint>

#define DIM 128
#define NN 200000
#define NE 12800000
#define SCAN_B 1024
#define NBLK 196            // 196*1024 = 200704 >= NN
#define FT 128              // fused m-tile
#define NTILE ((NN + FT - 1) / FT)   // 1563

// Static device scratch (no cudaMalloc allowed).
__device__ float    g_side[(size_t)NN * DIM];   // 102.4 MB result of SpMM
__device__ __half   g_ego_h[(size_t)NN * DIM];  // 51.2 MB fp16 gather copy
__device__ unsigned g_pay[NE];                  // 51.2 MB packed (col<<14 | q14)
__device__ int      g_cnt[NBLK * SCAN_B];       // histogram (zeroed by scan_fused)
__device__ int      g_woff[NN];                 // running offsets for scatter
__device__ int      g_rowptr[NN + 1];
__device__ int      g_bsum[NBLK];
__device__ int      g_flag;                     // grid barrier counter

// ---------------------------------------------------------------------------
// HMMA helper: m16n8k16 row.col f32.f16.f16.f32 (base sm_80+ instruction,
// supported on plain sm_103 target — tcgen05 is NOT, per round-14 ptxas).
// ---------------------------------------------------------------------------
__device__ __forceinline__ void mma16816(float* c, const uint32_t* a,
                                         uint32_t b0, uint32_t b1) {
    asm volatile(
        "mma.sync.aligned.m16n8k16.row.col.f32.f16.f16.f32 "
        "{%0,%1,%2,%3}, {%4,%5,%6,%7}, {%8,%9}, {%0,%1,%2,%3};"
        : "+f"(c[0]), "+f"(c[1]), "+f"(c[2]), "+f"(c[3])
        : "r"(a[0]), "r"(a[1]), "r"(a[2]), "r"(a[3]), "r"(b0), "r"(b1));
}

// ---------------------------------------------------------------------------
// 1) prep (fp16 shadow of ego) + hist (row degree) + flag reset
// ---------------------------------------------------------------------------
__global__ void prephist_kernel(const float* __restrict__ ego,
                                const int* __restrict__ erow) {
    if (blockIdx.x == 0 && threadIdx.x == 0) g_flag = 0;
    size_t nthr = (size_t)gridDim.x * blockDim.x;
    size_t tid0 = (size_t)blockIdx.x * blockDim.x + threadIdx.x;
    size_t total = (size_t)NN * DIM / 8;
    for (size_t i = tid0; i < total; i += nthr) {
        float4 a = __ldg((const float4*)ego + 2 * i);
        float4 b = __ldg((const float4*)ego + 2 * i + 1);
        __half2 h[4];
        h[0] = __floats2half2_rn(a.x, a.y);
        h[1] = __floats2half2_rn(a.z, a.w);
        h[2] = __floats2half2_rn(b.x, b.y);
        h[3] = __floats2half2_rn(b.z, b.w);
        *((uint4*)g_ego_h + i) = *(uint4*)h;
    }
    for (size_t i = tid0; i < NE / 4; i += nthr) {
        int4 r = __ldg((const int4*)erow + i);
        atomicAdd(&g_cnt[r.x], 1);
        atomicAdd(&g_cnt[r.y], 1);
        atomicAdd(&g_cnt[r.z], 1);
        atomicAdd(&g_cnt[r.w], 1);
    }
}

// ---------------------------------------------------------------------------
// 2) single-kernel exclusive scan with grid-wide software barrier.
// ---------------------------------------------------------------------------
__global__ void scan_fused() {
    __shared__ int sh[SCAN_B];
    __shared__ int sb[256];
    int t = threadIdx.x;
    int b = blockIdx.x;
    int gid = b * SCAN_B + t;

    int v = g_cnt[gid];
    g_cnt[gid] = 0;
    sh[t] = v;
    __syncthreads();
    for (int off = 1; off < SCAN_B; off <<= 1) {
        int u = (t >= off) ? sh[t - off] : 0;
        __syncthreads();
        sh[t] += u;
        __syncthreads();
    }
    int excl = sh[t] - v;

    if (t == SCAN_B - 1) {
        g_bsum[b] = sh[t];
        __threadfence();
        atomicAdd(&g_flag, 1);
    }
    if (t == 0) {
        while (*(volatile int*)&g_flag < NBLK) { }
    }
    __syncthreads();

    if (t < 256) sb[t] = (t < NBLK) ? *(volatile int*)&g_bsum[t] : 0;
    __syncthreads();
    for (int off = 1; off < 256; off <<= 1) {
        int u = (t < 256 && t >= off) ? sb[t - off] : 0;
        __syncthreads();
        if (t < 256) sb[t] += u;
        __syncthreads();
    }
    int boff = (b == 0) ? 0 : sb[b - 1];

    int val = excl + boff;
    if (gid < NN) {
        g_rowptr[gid] = val;
        g_woff[gid] = val;
    }
    if (b == 0 && t == 0) g_rowptr[NN] = NE;
}

// ---------------------------------------------------------------------------
// 3) scatter edges into row-sorted packed payload (single pass, R10 config)
// ---------------------------------------------------------------------------
__global__ void scatter_kernel(const int* __restrict__ erow,
                               const int* __restrict__ ecol,
                               const float* __restrict__ eval) {
    int i0 = blockIdx.x * blockDim.x + threadIdx.x;
    int stride = gridDim.x * blockDim.x;
    for (int i = i0; i < NE / 4; i += stride) {
        int4   r = __ldg((const int4*)erow + i);
        int4   c = __ldg((const int4*)ecol + i);
        float4 v = __ldg((const float4*)eval + i);
        int p0 = atomicAdd(&g_woff[r.x], 1);
        int p1 = atomicAdd(&g_woff[r.y], 1);
        int p2 = atomicAdd(&g_woff[r.z], 1);
        int p3 = atomicAdd(&g_woff[r.w], 1);
        unsigned q0 = min(16383u, (unsigned)__float2int_rn(v.x * 16384.f));
        unsigned q1 = min(16383u, (unsigned)__float2int_rn(v.y * 16384.f));
        unsigned q2 = min(16383u, (unsigned)__float2int_rn(v.z * 16384.f));
        unsigned q3 = min(16383u, (unsigned)__float2int_rn(v.w * 16384.f));
        g_pay[p0] = ((unsigned)c.x << 14) | q0;
        g_pay[p1] = ((unsigned)c.y << 14) | q1;
        g_pay[p2] = ((unsigned)c.z << 14) | q2;
        g_pay[p3] = ((unsigned)c.w << 14) | q3;
    }
}

// ---------------------------------------------------------------------------
// 4) CSR SpMM (unchanged from R10): one warp per row, 2 edge groups x uint4.
// ---------------------------------------------------------------------------
__global__ __launch_bounds__(512)
void spmm_csr_kernel() {
    int lane = threadIdx.x & 31;
    int g    = lane >> 4;
    int l16  = lane & 15;
    int row = (blockIdx.x * blockDim.x + threadIdx.x) >> 5;
    if (row >= NN) return;

    int start = g_rowptr[row];
    int end   = g_rowptr[row + 1];

    float4 accA = make_float4(0.f, 0.f, 0.f, 0.f);
    float4 accB = make_float4(0.f, 0.f, 0.f, 0.f);
    const float INV = 1.f / 16384.f;

    for (int e0 = start; e0 < end; e0 += 32) {
        int idx = e0 + lane;
        unsigned pay = (idx < end) ? __ldg(g_pay + idx) : 0u;
        int cnt = min(32, end - e0);
        int j = 0;
        #pragma unroll 1
        for (; j + 8 <= cnt; j += 8) {
            unsigned pj[4];
            uint4 raw[4];
            #pragma unroll
            for (int u = 0; u < 4; u++)
                pj[u] = __shfl_sync(0xffffffffu, pay, j + 2 * u + g);
            #pragma unroll
            for (int u = 0; u < 4; u++)
                raw[u] = __ldg((const uint4*)(g_ego_h + (size_t)(pj[u] >> 14) * DIM) + l16);
            #pragma unroll
            for (int u = 0; u < 4; u++) {
                float v = (float)(pj[u] & 0x3FFFu) * INV;
                float2 f0 = __half22float2(*(__half2*)&raw[u].x);
                float2 f1 = __half22float2(*(__half2*)&raw[u].y);
                float2 f2 = __half22float2(*(__half2*)&raw[u].z);
                float2 f3 = __half22float2(*(__half2*)&raw[u].w);
                accA.x = fmaf(f0.x, v, accA.x);
                accA.y = fmaf(f0.y, v, accA.y);
                accA.z = fmaf(f1.x, v, accA.z);
                accA.w = fmaf(f1.y, v, accA.w);
                accB.x = fmaf(f2.x, v, accB.x);
                accB.y = fmaf(f2.y, v, accB.y);
                accB.z = fmaf(f3.x, v, accB.z);
                accB.w = fmaf(f3.y, v, accB.w);
            }
        }
        #pragma unroll 1
        for (; j < cnt; j += 2) {
            int src = j + g;
            bool valid = src < cnt;
            unsigned p = __shfl_sync(0xffffffffu, pay, valid ? src : (cnt - 1));
            if (valid) {
                float v = (float)(p & 0x3FFFu) * INV;
                uint4 raw = __ldg((const uint4*)(g_ego_h + (size_t)(p >> 14) * DIM) + l16);
                float2 f0 = __half22float2(*(__half2*)&raw.x);
                float2 f1 = __half22float2(*(__half2*)&raw.y);
                float2 f2 = __half22float2(*(__half2*)&raw.z);
                float2 f3 = __half22float2(*(__half2*)&raw.w);
                accA.x = fmaf(f0.x, v, accA.x);
                accA.y = fmaf(f0.y, v, accA.y);
                accA.z = fmaf(f1.x, v, accA.z);
                accA.w = fmaf(f1.y, v, accA.w);
                accB.x = fmaf(f2.x, v, accB.x);
                accB.y = fmaf(f2.y, v, accB.y);
                accB.z = fmaf(f3.x, v, accB.z);
                accB.w = fmaf(f3.y, v, accB.w);
            }
        }
    }

    accA.x += __shfl_xor_sync(0xffffffffu, accA.x, 16);
    accA.y += __shfl_xor_sync(0xffffffffu, accA.y, 16);
    accA.z += __shfl_xor_sync(0xffffffffu, accA.z, 16);
    accA.w += __shfl_xor_sync(0xffffffffu, accA.w, 16);
    accB.x += __shfl_xor_sync(0xffffffffu, accB.x, 16);
    accB.y += __shfl_xor_sync(0xffffffffu, accB.y, 16);
    accB.z += __shfl_xor_sync(0xffffffffu, accB.z, 16);
    accB.w += __shfl_xor_sync(0xffffffffu, accB.w, 16);

    if (g == 0) {
        float4* dst = (float4*)(g_side + (size_t)row * DIM + l16 * 8);
        dst[0] = accA;
        dst[1] = accB;
    }
}

// ---------------------------------------------------------------------------
// 5) fused bi-interaction via mma.sync m16n8k16 (f16 in, f32 accumulate).
//    Per CTA: 128 rows. 8 warps = 4(m) x 2(n); warp does 32 rows x 64 cols
//    of BOTH GEMMs. out = lrelu(add@W1+b1) + lrelu(prod@W2+b2).
// ---------------------------------------------------------------------------
#define AS 136                         // halves per A/B tile row (128 + pad)
#define TILE_B (128 * AS * 2)          // 34816 bytes per f16 tile
#define SM_AADD  0
#define SM_APROD (TILE_B)
#define SM_B1    (2 * TILE_B)
#define SM_B2    (3 * TILE_B)
#define SM_TOTAL (4 * TILE_B)          // 139264
#define STAGE_STRIDE 132

__global__ __launch_bounds__(256, 1)
void fused_mma_kernel(const float* __restrict__ ego,
                      const float* __restrict__ W1, const float* __restrict__ b1,
                      const float* __restrict__ W2, const float* __restrict__ b2,
                      float* __restrict__ out) {
    extern __shared__ char smem[];
    __half* sAadd  = (__half*)(smem + SM_AADD);
    __half* sAprod = (__half*)(smem + SM_APROD);
    __half* sB1    = (__half*)(smem + SM_B1);
    __half* sB2    = (__half*)(smem + SM_B2);

    int tid = threadIdx.x;
    int wid = tid >> 5;
    int lane = tid & 31;
    int m0 = blockIdx.x * FT;

    // Build W1^T / W2^T tiles: sB[n*AS + k] = W[k*128 + n]
    for (int idx = tid; idx < DIM * DIM; idx += 256) {
        int k = idx >> 7, n = idx & 127;
        sB1[n * AS + k] = __float2half(__ldg(W1 + k * DIM + n));
        sB2[n * AS + k] = __float2half(__ldg(W2 + k * DIM + n));
    }

    // Build A tiles: add = ego + side, prod = ego * side (fp16, row-major)
    const float4* ego4 = (const float4*)ego;
    const float4* side4 = (const float4*)g_side;
    for (int idx = tid; idx < FT * 16; idx += 256) {
        int m = idx >> 4, ch = idx & 15;     // 8-half chunks
        int mg = m0 + m;
        float4 e0, e1, s0, s1;
        if (mg < NN) {
            e0 = __ldg(ego4 + (size_t)mg * 32 + ch * 2);
            e1 = __ldg(ego4 + (size_t)mg * 32 + ch * 2 + 1);
            s0 = side4[(size_t)mg * 32 + ch * 2];
            s1 = side4[(size_t)mg * 32 + ch * 2 + 1];
        } else {
            e0 = e1 = s0 = s1 = make_float4(0.f, 0.f, 0.f, 0.f);
        }
        __half2 ah[4], ph[4];
        ah[0] = __floats2half2_rn(e0.x + s0.x, e0.y + s0.y);
        ah[1] = __floats2half2_rn(e0.z + s0.z, e0.w + s0.w);
        ah[2] = __floats2half2_rn(e1.x + s1.x, e1.y + s1.y);
        ah[3] = __floats2half2_rn(e1.z + s1.z, e1.w + s1.w);
        ph[0] = __floats2half2_rn(e0.x * s0.x, e0.y * s0.y);
        ph[1] = __floats2half2_rn(e0.z * s0.z, e0.w * s0.w);
        ph[2] = __floats2half2_rn(e1.x * s1.x, e1.y * s1.y);
        ph[3] = __floats2half2_rn(e1.z * s1.z, e1.w * s1.w);
        *(uint4*)(sAadd  + m * AS + ch * 8) = *(uint4*)ah;
        *(uint4*)(sAprod + m * AS + ch * 8) = *(uint4*)ph;
    }
    __syncthreads();

    int wm = wid & 3;        // m-block: rows wm*32 .. wm*32+31
    int wn = wid >> 2;       // n-block: cols wn*64 .. wn*64+63
    int lq = lane >> 2;      // 0..7
    int lr = lane & 3;       // 0..3

    float c1[2][8][4], c2[2][8][4];
    #pragma unroll
    for (int mt = 0; mt < 2; mt++)
        #pragma unroll
        for (int nt = 0; nt < 8; nt++)
            #pragma unroll
            for (int q = 0; q < 4; q++) { c1[mt][nt][q] = 0.f; c2[mt][nt][q] = 0.f; }

    #pragma unroll
    for (int s = 0; s < 8; s++) {
        int k0 = s * 16;
        // A fragments (m16n8k16 row-major layout)
        uint32_t aA[2][4], aP[2][4];
        #pragma unroll
        for (int mt = 0; mt < 2; mt++) {
            int row = wm * 32 + mt * 16 + lq;
            int base = row * AS + k0 + lr * 2;
            aA[mt][0] = *(const uint32_t*)(sAadd + base);
            aA[mt][1] = *(const uint32_t*)(sAadd + base + 8 * AS);
            aA[mt][2] = *(const uint32_t*)(sAadd + base + 8);
            aA[mt][3] = *(const uint32_t*)(sAadd + base + 8 * AS + 8);
            aP[mt][0] = *(const uint32_t*)(sAprod + base);
            aP[mt][1] = *(const uint32_t*)(sAprod + base + 8 * AS);
            aP[mt][2] = *(const uint32_t*)(sAprod + base + 8);
            aP[mt][3] = *(const uint32_t*)(sAprod + base + 8 * AS + 8);
        }
        #pragma unroll
        for (int nt = 0; nt < 8; nt++) {
            int n = wn * 64 + nt * 8 + lq;
            int bbase = n * AS + k0 + lr * 2;
            uint32_t b10 = *(const uint32_t*)(sB1 + bbase);
            uint32_t b11 = *(const uint32_t*)(sB1 + bbase + 8);
            uint32_t b20 = *(const uint32_t*)(sB2 + bbase);
            uint32_t b21 = *(const uint32_t*)(sB2 + bbase + 8);
            mma16816(c1[0][nt], aA[0], b10, b11);
            mma16816(c1[1][nt], aA[1], b10, b11);
            mma16816(c2[0][nt], aP[0], b20, b21);
            mma16816(c2[1][nt], aP[1], b20, b21);
        }
    }
    __syncthreads();   // A/B tiles dead; reuse smem as fp32 stage

    // Epilogue: bias + leaky-relu per GEMM, sum, stage in smem
    float* stage = (float*)smem;   // [128][132] fp32 = 67584 B (fits in A area)
    #pragma unroll
    for (int mt = 0; mt < 2; mt++) {
        #pragma unroll
        for (int nt = 0; nt < 8; nt++) {
            int row = wm * 32 + mt * 16 + lq;
            int col = wn * 64 + nt * 8 + lr * 2;
            float2 bb1 = *(const float2*)(b1 + col);
            float2 bb2 = *(const float2*)(b2 + col);
            float x0 = c1[mt][nt][0] + bb1.x;
            float x1 = c1[mt][nt][1] + bb1.y;
            float y0 = c2[mt][nt][0] + bb2.x;
            float y1 = c2[mt][nt][1] + bb2.y;
            float r0 = (x0 > 0.f ? x0 : 0.01f * x0) + (y0 > 0.f ? y0 : 0.01f * y0);
            float r1 = (x1 > 0.f ? x1 : 0.01f * x1) + (y1 > 0.f ? y1 : 0.01f * y1);
            *(float2*)(stage + row * STAGE_STRIDE + col) = make_float2(r0, r1);
            float x2 = c1[mt][nt][2] + bb1.x;
            float x3 = c1[mt][nt][3] + bb1.y;
            float y2 = c2[mt][nt][2] + bb2.x;
            float y3 = c2[mt][nt][3] + bb2.y;
            float r2 = (x2 > 0.f ? x2 : 0.01f * x2) + (y2 > 0.f ? y2 : 0.01f * y2);
            float r3 = (x3 > 0.f ? x3 : 0.01f * x3) + (y3 > 0.f ? y3 : 0.01f * y3);
            *(float2*)(stage + (row + 8) * STAGE_STRIDE + col) = make_float2(r2, r3);
        }
    }
    __syncthreads();

    // Coalesced store
    for (int idx = tid; idx < FT * 32; idx += 256) {
        int m = idx >> 5, c4 = idx & 31;
        int mg = m0 + m;
        if (mg < NN) {
            float4 v = *(float4*)(stage + m * STAGE_STRIDE + c4 * 4);
            *((float4*)(out + (size_t)mg * DIM) + c4) = v;
        }
    }
}

// ---------------------------------------------------------------------------
extern "C" void kernel_launch(void* const* d_in, const int* in_sizes, int n_in,
                              void* d_out, int out_size) {
    const int*   erow = (const int*)d_in[0];
    const int*   ecol = (const int*)d_in[1];
    const float* eval = (const float*)d_in[2];
    const float* ego  = (const float*)d_in[3];
    const float* W1   = (const float*)d_in[4];
    const float* b1   = (const float*)d_in[5];
    const float* W2   = (const float*)d_in[6];
    const float* b2   = (const float*)d_in[7];
    float* out = (float*)d_out;

    cudaFuncSetAttribute(fused_mma_kernel,
                         cudaFuncAttributeMaxDynamicSharedMemorySize, SM_TOTAL);

    prephist_kernel<<<2048, 256>>>(ego, erow);             // launch 1
    scan_fused<<<NBLK, SCAN_B>>>();                        // launch 2
    scatter_kernel<<<2048, 256>>>(erow, ecol, eval);       // launch 3
    spmm_csr_kernel<<<(NN * 32 + 511) / 512, 512>>>();     // launch 4 (profiled)
    fused_mma_kernel<<<NTILE, 256, SM_TOTAL>>>(ego, W1, b1, W2, b2, out);
}

// round 16
// speedup vs baseline: 4.3597x; 1.2935x over previous
#include <cuda_runtime.h>
#include <cuda_fp16.h>
#include <cstdint>

#define DIM 128
#define NN 200000
#define NE 12800000
#define SCAN_B 1024
#define NBLK 196            // 196*1024 = 200704 >= NN
#define FT 128              // fused m-tile
#define NTILE ((NN + FT - 1) / FT)   // 1563

// Static device scratch (no cudaMalloc allowed).
__device__ float    g_side[(size_t)NN * DIM];   // 102.4 MB result of SpMM
__device__ __half   g_ego_h[(size_t)NN * DIM];  // 51.2 MB fp16 gather copy
__device__ unsigned g_pay[NE];                  // 51.2 MB packed (col<<14 | q14)
__device__ int      g_cnt[NBLK * SCAN_B];       // histogram (zeroed by scan_fused)
__device__ int      g_woff[NN];                 // running offsets for scatter
__device__ int      g_rowptr[NN + 1];
__device__ int      g_bsum[NBLK];
__device__ int      g_flag;                     // grid barrier counter

// ---------------------------------------------------------------------------
// HMMA helpers (base sm_80+ instructions; tcgen05 is sm_103a-only and the
// harness compiles for plain sm_103 — confirmed round 14).
// ---------------------------------------------------------------------------
__device__ __forceinline__ void mma16816(float* c, const uint32_t* a,
                                         uint32_t b0, uint32_t b1) {
    asm volatile(
        "mma.sync.aligned.m16n8k16.row.col.f32.f16.f16.f32 "
        "{%0,%1,%2,%3}, {%4,%5,%6,%7}, {%8,%9}, {%0,%1,%2,%3};"
        : "+f"(c[0]), "+f"(c[1]), "+f"(c[2]), "+f"(c[3])
        : "r"(a[0]), "r"(a[1]), "r"(a[2]), "r"(a[3]), "r"(b0), "r"(b1));
}
__device__ __forceinline__ void ldsm_x4(uint32_t* r, uint32_t saddr) {
    asm volatile(
        "ldmatrix.sync.aligned.m8n8.x4.shared.b16 {%0,%1,%2,%3}, [%4];"
        : "=r"(r[0]), "=r"(r[1]), "=r"(r[2]), "=r"(r[3]) : "r"(saddr));
}
__device__ __forceinline__ uint32_t smem_u32(const void* p) {
    uint32_t a;
    asm("{ .reg .u64 t; cvta.to.shared.u64 t, %1; cvt.u32.u64 %0, t; }"
        : "=r"(a) : "l"(p));
    return a;
}

// ---------------------------------------------------------------------------
// 1) prep (fp16 shadow of ego) + hist (row degree) + flag reset
// ---------------------------------------------------------------------------
__global__ void prephist_kernel(const float* __restrict__ ego,
                                const int* __restrict__ erow) {
    if (blockIdx.x == 0 && threadIdx.x == 0) g_flag = 0;
    size_t nthr = (size_t)gridDim.x * blockDim.x;
    size_t tid0 = (size_t)blockIdx.x * blockDim.x + threadIdx.x;
    size_t total = (size_t)NN * DIM / 8;
    for (size_t i = tid0; i < total; i += nthr) {
        float4 a = __ldg((const float4*)ego + 2 * i);
        float4 b = __ldg((const float4*)ego + 2 * i + 1);
        __half2 h[4];
        h[0] = __floats2half2_rn(a.x, a.y);
        h[1] = __floats2half2_rn(a.z, a.w);
        h[2] = __floats2half2_rn(b.x, b.y);
        h[3] = __floats2half2_rn(b.z, b.w);
        *((uint4*)g_ego_h + i) = *(uint4*)h;
    }
    for (size_t i = tid0; i < NE / 4; i += nthr) {
        int4 r = __ldg((const int4*)erow + i);
        atomicAdd(&g_cnt[r.x], 1);
        atomicAdd(&g_cnt[r.y], 1);
        atomicAdd(&g_cnt[r.z], 1);
        atomicAdd(&g_cnt[r.w], 1);
    }
}

// ---------------------------------------------------------------------------
// 2) single-kernel exclusive scan with grid-wide software barrier.
// ---------------------------------------------------------------------------
__global__ void scan_fused() {
    __shared__ int sh[SCAN_B];
    __shared__ int sb[256];
    int t = threadIdx.x;
    int b = blockIdx.x;
    int gid = b * SCAN_B + t;

    int v = g_cnt[gid];
    g_cnt[gid] = 0;
    sh[t] = v;
    __syncthreads();
    for (int off = 1; off < SCAN_B; off <<= 1) {
        int u = (t >= off) ? sh[t - off] : 0;
        __syncthreads();
        sh[t] += u;
        __syncthreads();
    }
    int excl = sh[t] - v;

    if (t == SCAN_B - 1) {
        g_bsum[b] = sh[t];
        __threadfence();
        atomicAdd(&g_flag, 1);
    }
    if (t == 0) {
        while (*(volatile int*)&g_flag < NBLK) { }
    }
    __syncthreads();

    if (t < 256) sb[t] = (t < NBLK) ? *(volatile int*)&g_bsum[t] : 0;
    __syncthreads();
    for (int off = 1; off < 256; off <<= 1) {
        int u = (t < 256 && t >= off) ? sb[t - off] : 0;
        __syncthreads();
        if (t < 256) sb[t] += u;
        __syncthreads();
    }
    int boff = (b == 0) ? 0 : sb[b - 1];

    int val = excl + boff;
    if (gid < NN) {
        g_rowptr[gid] = val;
        g_woff[gid] = val;
    }
    if (b == 0 && t == 0) g_rowptr[NN] = NE;
}

// ---------------------------------------------------------------------------
// 3) scatter edges into row-sorted packed payload (single pass)
// ---------------------------------------------------------------------------
__global__ void scatter_kernel(const int* __restrict__ erow,
                               const int* __restrict__ ecol,
                               const float* __restrict__ eval) {
    int i0 = blockIdx.x * blockDim.x + threadIdx.x;
    int stride = gridDim.x * blockDim.x;
    for (int i = i0; i < NE / 4; i += stride) {
        int4   r = __ldg((const int4*)erow + i);
        int4   c = __ldg((const int4*)ecol + i);
        float4 v = __ldg((const float4*)eval + i);
        int p0 = atomicAdd(&g_woff[r.x], 1);
        int p1 = atomicAdd(&g_woff[r.y], 1);
        int p2 = atomicAdd(&g_woff[r.z], 1);
        int p3 = atomicAdd(&g_woff[r.w], 1);
        unsigned q0 = min(16383u, (unsigned)__float2int_rn(v.x * 16384.f));
        unsigned q1 = min(16383u, (unsigned)__float2int_rn(v.y * 16384.f));
        unsigned q2 = min(16383u, (unsigned)__float2int_rn(v.z * 16384.f));
        unsigned q3 = min(16383u, (unsigned)__float2int_rn(v.w * 16384.f));
        g_pay[p0] = ((unsigned)c.x << 14) | q0;
        g_pay[p1] = ((unsigned)c.y << 14) | q1;
        g_pay[p2] = ((unsigned)c.z << 14) | q2;
        g_pay[p3] = ((unsigned)c.w << 14) | q3;
    }
}

// ---------------------------------------------------------------------------
// 4) CSR SpMM: one warp per row, 2 edge groups x uint4; per-lane {off,v}
//    precomputed once per 32-edge block, then shuffled (saves AND/I2F/FMUL).
// ---------------------------------------------------------------------------
__global__ __launch_bounds__(512)
void spmm_csr_kernel() {
    int lane = threadIdx.x & 31;
    int g    = lane >> 4;
    int l16  = lane & 15;
    int row = (blockIdx.x * blockDim.x + threadIdx.x) >> 5;
    if (row >= NN) return;

    int start = g_rowptr[row];
    int end   = g_rowptr[row + 1];

    float4 accA = make_float4(0.f, 0.f, 0.f, 0.f);
    float4 accB = make_float4(0.f, 0.f, 0.f, 0.f);
    const float INV = 1.f / 16384.f;
    const char* ebase = (const char*)g_ego_h;

    for (int e0 = start; e0 < end; e0 += 32) {
        int idx = e0 + lane;
        unsigned pay = (idx < end) ? __ldg(g_pay + idx) : 0u;
        unsigned off = (pay >> 14) << 8;            // col * 256 bytes
        int      vi  = __float_as_int((float)(pay & 0x3FFFu) * INV);
        int cnt = min(32, end - e0);
        int j = 0;
        #pragma unroll 1
        for (; j + 8 <= cnt; j += 8) {
            unsigned oj[4];
            float    vj[4];
            uint4 raw[4];
            #pragma unroll
            for (int u = 0; u < 4; u++) {
                int src = j + 2 * u + g;
                oj[u] = __shfl_sync(0xffffffffu, off, src);
                vj[u] = __int_as_float(__shfl_sync(0xffffffffu, vi, src));
            }
            #pragma unroll
            for (int u = 0; u < 4; u++)
                raw[u] = __ldg((const uint4*)(ebase + oj[u]) + l16);
            #pragma unroll
            for (int u = 0; u < 4; u++) {
                float v = vj[u];
                float2 f0 = __half22float2(*(__half2*)&raw[u].x);
                float2 f1 = __half22float2(*(__half2*)&raw[u].y);
                float2 f2 = __half22float2(*(__half2*)&raw[u].z);
                float2 f3 = __half22float2(*(__half2*)&raw[u].w);
                accA.x = fmaf(f0.x, v, accA.x);
                accA.y = fmaf(f0.y, v, accA.y);
                accA.z = fmaf(f1.x, v, accA.z);
                accA.w = fmaf(f1.y, v, accA.w);
                accB.x = fmaf(f2.x, v, accB.x);
                accB.y = fmaf(f2.y, v, accB.y);
                accB.z = fmaf(f3.x, v, accB.z);
                accB.w = fmaf(f3.y, v, accB.w);
            }
        }
        #pragma unroll 1
        for (; j < cnt; j += 2) {
            int src = j + g;
            bool valid = src < cnt;
            int pick = valid ? src : (cnt - 1);
            unsigned o = __shfl_sync(0xffffffffu, off, pick);
            float    v = __int_as_float(__shfl_sync(0xffffffffu, vi, pick));
            if (valid) {
                uint4 raw = __ldg((const uint4*)(ebase + o) + l16);
                float2 f0 = __half22float2(*(__half2*)&raw.x);
                float2 f1 = __half22float2(*(__half2*)&raw.y);
                float2 f2 = __half22float2(*(__half2*)&raw.z);
                float2 f3 = __half22float2(*(__half2*)&raw.w);
                accA.x = fmaf(f0.x, v, accA.x);
                accA.y = fmaf(f0.y, v, accA.y);
                accA.z = fmaf(f1.x, v, accA.z);
                accA.w = fmaf(f1.y, v, accA.w);
                accB.x = fmaf(f2.x, v, accB.x);
                accB.y = fmaf(f2.y, v, accB.y);
                accB.z = fmaf(f3.x, v, accB.z);
                accB.w = fmaf(f3.y, v, accB.w);
            }
        }
    }

    accA.x += __shfl_xor_sync(0xffffffffu, accA.x, 16);
    accA.y += __shfl_xor_sync(0xffffffffu, accA.y, 16);
    accA.z += __shfl_xor_sync(0xffffffffu, accA.z, 16);
    accA.w += __shfl_xor_sync(0xffffffffu, accA.w, 16);
    accB.x += __shfl_xor_sync(0xffffffffu, accB.x, 16);
    accB.y += __shfl_xor_sync(0xffffffffu, accB.y, 16);
    accB.z += __shfl_xor_sync(0xffffffffu, accB.z, 16);
    accB.w += __shfl_xor_sync(0xffffffffu, accB.w, 16);

    if (g == 0) {
        float4* dst = (float4*)(g_side + (size_t)row * DIM + l16 * 8);
        dst[0] = accA;
        dst[1] = accB;
    }
}

// ---------------------------------------------------------------------------
// 5) fused bi-interaction via mma.sync m16n8k16 + ldmatrix fragment loads.
//    Per CTA: 128 rows. 8 warps = 4(m) x 2(n); warp: 32 rows x 64 cols, both GEMMs.
// ---------------------------------------------------------------------------
#define AS 136                         // halves per A/B tile row (128 + pad)
#define TILE_B (128 * AS * 2)          // 34816 bytes per f16 tile
#define SM_AADD  0
#define SM_APROD (TILE_B)
#define SM_B1    (2 * TILE_B)
#define SM_B2    (3 * TILE_B)
#define SM_TOTAL (4 * TILE_B)          // 139264
#define STAGE_STRIDE 132

__global__ __launch_bounds__(256, 1)
void fused_mma_kernel(const float* __restrict__ ego,
                      const float* __restrict__ W1, const float* __restrict__ b1,
                      const float* __restrict__ W2, const float* __restrict__ b2,
                      float* __restrict__ out) {
    extern __shared__ char smem[];
    __half* sAadd  = (__half*)(smem + SM_AADD);
    __half* sAprod = (__half*)(smem + SM_APROD);
    __half* sB1    = (__half*)(smem + SM_B1);
    __half* sB2    = (__half*)(smem + SM_B2);

    int tid = threadIdx.x;
    int wid = tid >> 5;
    int lane = tid & 31;
    int m0 = blockIdx.x * FT;

    // Build W1^T / W2^T tiles: sB[n*AS + k] = W[k*128 + n]
    for (int idx = tid; idx < DIM * DIM; idx += 256) {
        int k = idx >> 7, n = idx & 127;
        sB1[n * AS + k] = __float2half(__ldg(W1 + k * DIM + n));
        sB2[n * AS + k] = __float2half(__ldg(W2 + k * DIM + n));
    }

    // Build A tiles: add = ego + side, prod = ego * side (fp16, row-major)
    const float4* ego4 = (const float4*)ego;
    const float4* side4 = (const float4*)g_side;
    for (int idx = tid; idx < FT * 16; idx += 256) {
        int m = idx >> 4, ch = idx & 15;
        int mg = m0 + m;
        float4 e0, e1, s0, s1;
        if (mg < NN) {
            e0 = __ldg(ego4 + (size_t)mg * 32 + ch * 2);
            e1 = __ldg(ego4 + (size_t)mg * 32 + ch * 2 + 1);
            s0 = side4[(size_t)mg * 32 + ch * 2];
            s1 = side4[(size_t)mg * 32 + ch * 2 + 1];
        } else {
            e0 = e1 = s0 = s1 = make_float4(0.f, 0.f, 0.f, 0.f);
        }
        __half2 ah[4], ph[4];
        ah[0] = __floats2half2_rn(e0.x + s0.x, e0.y + s0.y);
        ah[1] = __floats2half2_rn(e0.z + s0.z, e0.w + s0.w);
        ah[2] = __floats2half2_rn(e1.x + s1.x, e1.y + s1.y);
        ah[3] = __floats2half2_rn(e1.z + s1.z, e1.w + s1.w);
        ph[0] = __floats2half2_rn(e0.x * s0.x, e0.y * s0.y);
        ph[1] = __floats2half2_rn(e0.z * s0.z, e0.w * s0.w);
        ph[2] = __floats2half2_rn(e1.x * s1.x, e1.y * s1.y);
        ph[3] = __floats2half2_rn(e1.z * s1.z, e1.w * s1.w);
        *(uint4*)(sAadd  + m * AS + ch * 8) = *(uint4*)ah;
        *(uint4*)(sAprod + m * AS + ch * 8) = *(uint4*)ph;
    }
    __syncthreads();

    int wm = wid & 3;        // m-block: rows wm*32 .. +31
    int wn = wid >> 2;       // n-block: cols wn*64 .. +63
    int lq = lane >> 2;      // 0..7 (epilogue row/col mapping)
    int lr = lane & 3;       // 0..3

    // ldmatrix lane-address components
    uint32_t sA_add  = smem_u32(sAadd);
    uint32_t sA_prod = smem_u32(sAprod);
    uint32_t sB1a    = smem_u32(sB1);
    uint32_t sB2a    = smem_u32(sB2);
    int a_lrow  = lane & 15;             // A: row within 16-block
    int a_khalf = (lane >> 4) * 8;       // A: +8 k for upper 16 lanes
    int b_seg   = lane >> 3;             // B: 4 segments of 8 lanes
    int b_noff  = ((b_seg >> 1) * 8) + (lane & 7);   // n offset
    int b_koff  = (b_seg & 1) * 8;                   // k offset

    float c1[2][8][4], c2[2][8][4];
    #pragma unroll
    for (int mt = 0; mt < 2; mt++)
        #pragma unroll
        for (int nt = 0; nt < 8; nt++)
            #pragma unroll
            for (int q = 0; q < 4; q++) { c1[mt][nt][q] = 0.f; c2[mt][nt][q] = 0.f; }

    #pragma unroll
    for (int s = 0; s < 8; s++) {
        int k0 = s * 16;
        uint32_t aA[2][4], aP[2][4];
        #pragma unroll
        for (int mt = 0; mt < 2; mt++) {
            uint32_t roff = (uint32_t)((wm * 32 + mt * 16 + a_lrow) * AS
                                       + k0 + a_khalf) * 2;
            ldsm_x4(aA[mt], sA_add + roff);
            ldsm_x4(aP[mt], sA_prod + roff);
        }
        uint32_t bf1[8][2], bf2[8][2];
        #pragma unroll
        for (int q = 0; q < 4; q++) {
            int n0 = wn * 64 + q * 16;
            uint32_t boff = (uint32_t)((n0 + b_noff) * AS + k0 + b_koff) * 2;
            uint32_t t1[4], t2[4];
            ldsm_x4(t1, sB1a + boff);
            ldsm_x4(t2, sB2a + boff);
            bf1[2 * q][0] = t1[0]; bf1[2 * q][1] = t1[1];
            bf1[2 * q + 1][0] = t1[2]; bf1[2 * q + 1][1] = t1[3];
            bf2[2 * q][0] = t2[0]; bf2[2 * q][1] = t2[1];
            bf2[2 * q + 1][0] = t2[2]; bf2[2 * q + 1][1] = t2[3];
        }
        #pragma unroll
        for (int nt = 0; nt < 8; nt++) {
            mma16816(c1[0][nt], aA[0], bf1[nt][0], bf1[nt][1]);
            mma16816(c1[1][nt], aA[1], bf1[nt][0], bf1[nt][1]);
            mma16816(c2[0][nt], aP[0], bf2[nt][0], bf2[nt][1]);
            mma16816(c2[1][nt], aP[1], bf2[nt][0], bf2[nt][1]);
        }
    }
    __syncthreads();   // A/B tiles dead; reuse smem as fp32 stage

    // Epilogue: bias + leaky-relu per GEMM, sum, stage in smem
    float* stage = (float*)smem;   // [128][132] fp32
    #pragma unroll
    for (int mt = 0; mt < 2; mt++) {
        #pragma unroll
        for (int nt = 0; nt < 8; nt++) {
            int row = wm * 32 + mt * 16 + lq;
            int col = wn * 64 + nt * 8 + lr * 2;
            float2 bb1 = *(const float2*)(b1 + col);
            float2 bb2 = *(const float2*)(b2 + col);
            float x0 = c1[mt][nt][0] + bb1.x;
            float x1 = c1[mt][nt][1] + bb1.y;
            float y0 = c2[mt][nt][0] + bb2.x;
            float y1 = c2[mt][nt][1] + bb2.y;
            float r0 = (x0 > 0.f ? x0 : 0.01f * x0) + (y0 > 0.f ? y0 : 0.01f * y0);
            float r1 = (x1 > 0.f ? x1 : 0.01f * x1) + (y1 > 0.f ? y1 : 0.01f * y1);
            *(float2*)(stage + row * STAGE_STRIDE + col) = make_float2(r0, r1);
            float x2 = c1[mt][nt][2] + bb1.x;
            float x3 = c1[mt][nt][3] + bb1.y;
            float y2 = c2[mt][nt][2] + bb2.x;
            float y3 = c2[mt][nt][3] + bb2.y;
            float r2 = (x2 > 0.f ? x2 : 0.01f * x2) + (y2 > 0.f ? y2 : 0.01f * y2);
            float r3 = (x3 > 0.f ? x3 : 0.01f * x3) + (y3 > 0.f ? y3 : 0.01f * y3);
            *(float2*)(stage + (row + 8) * STAGE_STRIDE + col) = make_float2(r2, r3);
        }
    }
    __syncthreads();

    // Coalesced store
    for (int idx = tid; idx < FT * 32; idx += 256) {
        int m = idx >> 5, c4 = idx & 31;
        int mg = m0 + m;
        if (mg < NN) {
            float4 v = *(float4*)(stage + m * STAGE_STRIDE + c4 * 4);
            *((float4*)(out + (size_t)mg * DIM) + c4) = v;
        }
    }
}

// ---------------------------------------------------------------------------
extern "C" void kernel_launch(void* const* d_in, const int* in_sizes, int n_in,
                              void* d_out, int out_size) {
    const int*   erow = (const int*)d_in[0];
    const int*   ecol = (const int*)d_in[1];
    const float* eval = (const float*)d_in[2];
    const float* ego  = (const float*)d_in[3];
    const float* W1   = (const float*)d_in[4];
    const float* b1   = (const float*)d_in[5];
    const float* W2   = (const float*)d_in[6];
    const float* b2   = (const float*)d_in[7];
    float* out = (float*)d_out;

    cudaFuncSetAttribute(fused_mma_kernel,
                         cudaFuncAttributeMaxDynamicSharedMemorySize, SM_TOTAL);

    prephist_kernel<<<2048, 256>>>(ego, erow);             // launch 1
    scan_fused<<<NBLK, SCAN_B>>>();                        // launch 2
    scatter_kernel<<<2048, 256>>>(erow, ecol, eval);       // launch 3
    spmm_csr_kernel<<<(NN * 32 + 511) / 512, 512>>>();     // launch 4 (profiled)
    fused_mma_kernel<<<NTILE, 256, SM_TOTAL>>>(ego, W1, b1, W2, b2, out);
}

// round 17
// speedup vs baseline: 4.4750x; 1.0264x over previous
#include <cuda_runtime.h>
#include <cuda_fp16.h>
#include <cstdint>

#define DIM 128
#define NN 200000
#define NE 12800000
#define SCAN_B 1024
#define NBLK 196            // 196*1024 = 200704 >= NN
#define FT 128              // fused m-tile
#define NTILE ((NN + FT - 1) / FT)   // 1563

// Static device scratch (no cudaMalloc allowed).
__device__ float    g_side[(size_t)NN * DIM];   // 102.4 MB result of SpMM
__device__ __half   g_ego_h[(size_t)NN * DIM];  // 51.2 MB fp16 gather copy
__device__ unsigned g_pay[NE];                  // 51.2 MB packed (col<<14 | q14)
__device__ int      g_cnt[NBLK * SCAN_B];       // histogram (zeroed by scan_fused)
__device__ int      g_woff[NN];                 // running offsets for scatter
__device__ int      g_rowptr[NN + 1];
__device__ int      g_bsum[NBLK];
__device__ int      g_flag;                     // grid barrier counter

// ---------------------------------------------------------------------------
// HMMA / mixed-precision helpers (base sm_100-family PTX; no 'a' features)
// ---------------------------------------------------------------------------
__device__ __forceinline__ void mma16816(float* c, const uint32_t* a,
                                         uint32_t b0, uint32_t b1) {
    asm volatile(
        "mma.sync.aligned.m16n8k16.row.col.f32.f16.f16.f32 "
        "{%0,%1,%2,%3}, {%4,%5,%6,%7}, {%8,%9}, {%0,%1,%2,%3};"
        : "+f"(c[0]), "+f"(c[1]), "+f"(c[2]), "+f"(c[3])
        : "r"(a[0]), "r"(a[1]), "r"(a[2]), "r"(a[3]), "r"(b0), "r"(b1));
}
__device__ __forceinline__ void ldsm_x4(uint32_t* r, uint32_t saddr) {
    asm volatile(
        "ldmatrix.sync.aligned.m8n8.x4.shared.b16 {%0,%1,%2,%3}, [%4];"
        : "=r"(r[0]), "=r"(r[1]), "=r"(r[2]), "=r"(r[3]) : "r"(saddr));
}
__device__ __forceinline__ uint32_t smem_u32(const void* p) {
    uint32_t a;
    asm("{ .reg .u64 t; cvta.to.shared.u64 t, %1; cvt.u32.u64 %0, t; }"
        : "=r"(a) : "l"(p));
    return a;
}
// mixed-precision FMA: two f16 lanes of `packed` times f16 `v`, f32 accumulate
__device__ __forceinline__ void fma_h2_f32(float& a0, float& a1,
                                           uint32_t packed, uint16_t v) {
    asm("{\n\t"
        ".reg .b16 lo, hi;\n\t"
        "mov.b32 {lo, hi}, %2;\n\t"
        "fma.rn.f32.f16 %0, lo, %3, %0;\n\t"
        "fma.rn.f32.f16 %1, hi, %3, %1;\n\t"
        "}" : "+f"(a0), "+f"(a1) : "r"(packed), "h"(v));
}

// ---------------------------------------------------------------------------
// 1) prep (fp16 shadow of ego) + hist (row degree) + flag reset
// ---------------------------------------------------------------------------
__global__ void prephist_kernel(const float* __restrict__ ego,
                                const int* __restrict__ erow) {
    if (blockIdx.x == 0 && threadIdx.x == 0) g_flag = 0;
    size_t nthr = (size_t)gridDim.x * blockDim.x;
    size_t tid0 = (size_t)blockIdx.x * blockDim.x + threadIdx.x;
    size_t total = (size_t)NN * DIM / 8;
    for (size_t i = tid0; i < total; i += nthr) {
        float4 a = __ldg((const float4*)ego + 2 * i);
        float4 b = __ldg((const float4*)ego + 2 * i + 1);
        __half2 h[4];
        h[0] = __floats2half2_rn(a.x, a.y);
        h[1] = __floats2half2_rn(a.z, a.w);
        h[2] = __floats2half2_rn(b.x, b.y);
        h[3] = __floats2half2_rn(b.z, b.w);
        *((uint4*)g_ego_h + i) = *(uint4*)h;
    }
    for (size_t i = tid0; i < NE / 4; i += nthr) {
        int4 r = __ldg((const int4*)erow + i);
        atomicAdd(&g_cnt[r.x], 1);
        atomicAdd(&g_cnt[r.y], 1);
        atomicAdd(&g_cnt[r.z], 1);
        atomicAdd(&g_cnt[r.w], 1);
    }
}

// ---------------------------------------------------------------------------
// 2) single-kernel exclusive scan with grid-wide software barrier.
// ---------------------------------------------------------------------------
__global__ void scan_fused() {
    __shared__ int sh[SCAN_B];
    __shared__ int sb[256];
    int t = threadIdx.x;
    int b = blockIdx.x;
    int gid = b * SCAN_B + t;

    int v = g_cnt[gid];
    g_cnt[gid] = 0;
    sh[t] = v;
    __syncthreads();
    for (int off = 1; off < SCAN_B; off <<= 1) {
        int u = (t >= off) ? sh[t - off] : 0;
        __syncthreads();
        sh[t] += u;
        __syncthreads();
    }
    int excl = sh[t] - v;

    if (t == SCAN_B - 1) {
        g_bsum[b] = sh[t];
        __threadfence();
        atomicAdd(&g_flag, 1);
    }
    if (t == 0) {
        while (*(volatile int*)&g_flag < NBLK) { }
    }
    __syncthreads();

    if (t < 256) sb[t] = (t < NBLK) ? *(volatile int*)&g_bsum[t] : 0;
    __syncthreads();
    for (int off = 1; off < 256; off <<= 1) {
        int u = (t < 256 && t >= off) ? sb[t - off] : 0;
        __syncthreads();
        if (t < 256) sb[t] += u;
        __syncthreads();
    }
    int boff = (b == 0) ? 0 : sb[b - 1];

    int val = excl + boff;
    if (gid < NN) {
        g_rowptr[gid] = val;
        g_woff[gid] = val;
    }
    if (b == 0 && t == 0) g_rowptr[NN] = NE;
}

// ---------------------------------------------------------------------------
// 3) scatter edges into row-sorted packed payload (single pass)
// ---------------------------------------------------------------------------
__global__ void scatter_kernel(const int* __restrict__ erow,
                               const int* __restrict__ ecol,
                               const float* __restrict__ eval) {
    int i0 = blockIdx.x * blockDim.x + threadIdx.x;
    int stride = gridDim.x * blockDim.x;
    for (int i = i0; i < NE / 4; i += stride) {
        int4   r = __ldg((const int4*)erow + i);
        int4   c = __ldg((const int4*)ecol + i);
        float4 v = __ldg((const float4*)eval + i);
        int p0 = atomicAdd(&g_woff[r.x], 1);
        int p1 = atomicAdd(&g_woff[r.y], 1);
        int p2 = atomicAdd(&g_woff[r.z], 1);
        int p3 = atomicAdd(&g_woff[r.w], 1);
        unsigned q0 = min(16383u, (unsigned)__float2int_rn(v.x * 16384.f));
        unsigned q1 = min(16383u, (unsigned)__float2int_rn(v.y * 16384.f));
        unsigned q2 = min(16383u, (unsigned)__float2int_rn(v.z * 16384.f));
        unsigned q3 = min(16383u, (unsigned)__float2int_rn(v.w * 16384.f));
        g_pay[p0] = ((unsigned)c.x << 14) | q0;
        g_pay[p1] = ((unsigned)c.y << 14) | q1;
        g_pay[p2] = ((unsigned)c.z << 14) | q2;
        g_pay[p3] = ((unsigned)c.w << 14) | q3;
    }
}

// ---------------------------------------------------------------------------
// 4) CSR SpMM: one warp per row, 2 edge groups x uint4.
//    Mixed-precision fma.rn.f32.f16 removes the 8 CVTs per edge-lane;
//    v shuffled as fp16 bits (converted once per 32-edge block).
// ---------------------------------------------------------------------------
__global__ __launch_bounds__(512)
void spmm_csr_kernel() {
    int lane = threadIdx.x & 31;
    int g    = lane >> 4;
    int l16  = lane & 15;
    int row = (blockIdx.x * blockDim.x + threadIdx.x) >> 5;
    if (row >= NN) return;

    int start = g_rowptr[row];
    int end   = g_rowptr[row + 1];

    float4 accA = make_float4(0.f, 0.f, 0.f, 0.f);
    float4 accB = make_float4(0.f, 0.f, 0.f, 0.f);
    const float INV = 1.f / 16384.f;
    const char* ebase = (const char*)g_ego_h;

    for (int e0 = start; e0 < end; e0 += 32) {
        int idx = e0 + lane;
        unsigned pay = (idx < end) ? __ldg(g_pay + idx) : 0u;
        unsigned off = (pay >> 14) << 8;            // col * 256 bytes
        unsigned vh  = (unsigned)__half_as_ushort(
                           __float2half_rn((float)(pay & 0x3FFFu) * INV));
        int cnt = min(32, end - e0);
        int j = 0;
        #pragma unroll 1
        for (; j + 8 <= cnt; j += 8) {
            unsigned oj[4];
            uint16_t vj[4];
            uint4 raw[4];
            #pragma unroll
            for (int u = 0; u < 4; u++) {
                int src = j + 2 * u + g;
                oj[u] = __shfl_sync(0xffffffffu, off, src);
                vj[u] = (uint16_t)__shfl_sync(0xffffffffu, vh, src);
            }
            #pragma unroll
            for (int u = 0; u < 4; u++)
                raw[u] = __ldg((const uint4*)(ebase + oj[u]) + l16);
            #pragma unroll
            for (int u = 0; u < 4; u++) {
                fma_h2_f32(accA.x, accA.y, raw[u].x, vj[u]);
                fma_h2_f32(accA.z, accA.w, raw[u].y, vj[u]);
                fma_h2_f32(accB.x, accB.y, raw[u].z, vj[u]);
                fma_h2_f32(accB.z, accB.w, raw[u].w, vj[u]);
            }
        }
        #pragma unroll 1
        for (; j < cnt; j += 2) {
            int src = j + g;
            bool valid = src < cnt;
            int pick = valid ? src : (cnt - 1);
            unsigned o = __shfl_sync(0xffffffffu, off, pick);
            uint16_t v = (uint16_t)__shfl_sync(0xffffffffu, vh, pick);
            if (valid) {
                uint4 raw = __ldg((const uint4*)(ebase + o) + l16);
                fma_h2_f32(accA.x, accA.y, raw.x, v);
                fma_h2_f32(accA.z, accA.w, raw.y, v);
                fma_h2_f32(accB.x, accB.y, raw.z, v);
                fma_h2_f32(accB.z, accB.w, raw.w, v);
            }
        }
    }

    accA.x += __shfl_xor_sync(0xffffffffu, accA.x, 16);
    accA.y += __shfl_xor_sync(0xffffffffu, accA.y, 16);
    accA.z += __shfl_xor_sync(0xffffffffu, accA.z, 16);
    accA.w += __shfl_xor_sync(0xffffffffu, accA.w, 16);
    accB.x += __shfl_xor_sync(0xffffffffu, accB.x, 16);
    accB.y += __shfl_xor_sync(0xffffffffu, accB.y, 16);
    accB.z += __shfl_xor_sync(0xffffffffu, accB.z, 16);
    accB.w += __shfl_xor_sync(0xffffffffu, accB.w, 16);

    if (g == 0) {
        float4* dst = (float4*)(g_side + (size_t)row * DIM + l16 * 8);
        dst[0] = accA;
        dst[1] = accB;
    }
}

// ---------------------------------------------------------------------------
// 5) fused bi-interaction via mma.sync m16n8k16 + ldmatrix fragment loads.
// ---------------------------------------------------------------------------
#define AS 136                         // halves per A/B tile row (128 + pad)
#define TILE_B (128 * AS * 2)          // 34816 bytes per f16 tile
#define SM_AADD  0
#define SM_APROD (TILE_B)
#define SM_B1    (2 * TILE_B)
#define SM_B2    (3 * TILE_B)
#define SM_TOTAL (4 * TILE_B)          // 139264
#define STAGE_STRIDE 132

__global__ __launch_bounds__(256, 1)
void fused_mma_kernel(const float* __restrict__ ego,
                      const float* __restrict__ W1, const float* __restrict__ b1,
                      const float* __restrict__ W2, const float* __restrict__ b2,
                      float* __restrict__ out) {
    extern __shared__ char smem[];
    __half* sAadd  = (__half*)(smem + SM_AADD);
    __half* sAprod = (__half*)(smem + SM_APROD);
    __half* sB1    = (__half*)(smem + SM_B1);
    __half* sB2    = (__half*)(smem + SM_B2);

    int tid = threadIdx.x;
    int wid = tid >> 5;
    int lane = tid & 31;
    int m0 = blockIdx.x * FT;

    for (int idx = tid; idx < DIM * DIM; idx += 256) {
        int k = idx >> 7, n = idx & 127;
        sB1[n * AS + k] = __float2half(__ldg(W1 + k * DIM + n));
        sB2[n * AS + k] = __float2half(__ldg(W2 + k * DIM + n));
    }

    const float4* ego4 = (const float4*)ego;
    const float4* side4 = (const float4*)g_side;
    for (int idx = tid; idx < FT * 16; idx += 256) {
        int m = idx >> 4, ch = idx & 15;
        int mg = m0 + m;
        float4 e0, e1, s0, s1;
        if (mg < NN) {
            e0 = __ldg(ego4 + (size_t)mg * 32 + ch * 2);
            e1 = __ldg(ego4 + (size_t)mg * 32 + ch * 2 + 1);
            s0 = side4[(size_t)mg * 32 + ch * 2];
            s1 = side4[(size_t)mg * 32 + ch * 2 + 1];
        } else {
            e0 = e1 = s0 = s1 = make_float4(0.f, 0.f, 0.f, 0.f);
        }
        __half2 ah[4], ph[4];
        ah[0] = __floats2half2_rn(e0.x + s0.x, e0.y + s0.y);
        ah[1] = __floats2half2_rn(e0.z + s0.z, e0.w + s0.w);
        ah[2] = __floats2half2_rn(e1.x + s1.x, e1.y + s1.y);
        ah[3] = __floats2half2_rn(e1.z + s1.z, e1.w + s1.w);
        ph[0] = __floats2half2_rn(e0.x * s0.x, e0.y * s0.y);
        ph[1] = __floats2half2_rn(e0.z * s0.z, e0.w * s0.w);
        ph[2] = __floats2half2_rn(e1.x * s1.x, e1.y * s1.y);
        ph[3] = __floats2half2_rn(e1.z * s1.z, e1.w * s1.w);
        *(uint4*)(sAadd  + m * AS + ch * 8) = *(uint4*)ah;
        *(uint4*)(sAprod + m * AS + ch * 8) = *(uint4*)ph;
    }
    __syncthreads();

    int wm = wid & 3;
    int wn = wid >> 2;
    int lq = lane >> 2;
    int lr = lane & 3;

    uint32_t sA_add  = smem_u32(sAadd);
    uint32_t sA_prod = smem_u32(sAprod);
    uint32_t sB1a    = smem_u32(sB1);
    uint32_t sB2a    = smem_u32(sB2);
    int a_lrow  = lane & 15;
    int a_khalf = (lane >> 4) * 8;
    int b_seg   = lane >> 3;
    int b_noff  = ((b_seg >> 1) * 8) + (lane & 7);
    int b_koff  = (b_seg & 1) * 8;

    float c1[2][8][4], c2[2][8][4];
    #pragma unroll
    for (int mt = 0; mt < 2; mt++)
        #pragma unroll
        for (int nt = 0; nt < 8; nt++)
            #pragma unroll
            for (int q = 0; q < 4; q++) { c1[mt][nt][q] = 0.f; c2[mt][nt][q] = 0.f; }

    #pragma unroll
    for (int s = 0; s < 8; s++) {
        int k0 = s * 16;
        uint32_t aA[2][4], aP[2][4];
        #pragma unroll
        for (int mt = 0; mt < 2; mt++) {
            uint32_t roff = (uint32_t)((wm * 32 + mt * 16 + a_lrow) * AS
                                       + k0 + a_khalf) * 2;
            ldsm_x4(aA[mt], sA_add + roff);
            ldsm_x4(aP[mt], sA_prod + roff);
        }
        uint32_t bf1[8][2], bf2[8][2];
        #pragma unroll
        for (int q = 0; q < 4; q++) {
            int n0 = wn * 64 + q * 16;
            uint32_t boff = (uint32_t)((n0 + b_noff) * AS + k0 + b_koff) * 2;
            uint32_t t1[4], t2[4];
            ldsm_x4(t1, sB1a + boff);
            ldsm_x4(t2, sB2a + boff);
            bf1[2 * q][0] = t1[0]; bf1[2 * q][1] = t1[1];
            bf1[2 * q + 1][0] = t1[2]; bf1[2 * q + 1][1] = t1[3];
            bf2[2 * q][0] = t2[0]; bf2[2 * q][1] = t2[1];
            bf2[2 * q + 1][0] = t2[2]; bf2[2 * q + 1][1] = t2[3];
        }
        #pragma unroll
        for (int nt = 0; nt < 8; nt++) {
            mma16816(c1[0][nt], aA[0], bf1[nt][0], bf1[nt][1]);
            mma16816(c1[1][nt], aA[1], bf1[nt][0], bf1[nt][1]);
            mma16816(c2[0][nt], aP[0], bf2[nt][0], bf2[nt][1]);
            mma16816(c2[1][nt], aP[1], bf2[nt][0], bf2[nt][1]);
        }
    }
    __syncthreads();

    float* stage = (float*)smem;
    #pragma unroll
    for (int mt = 0; mt < 2; mt++) {
        #pragma unroll
        for (int nt = 0; nt < 8; nt++) {
            int row = wm * 32 + mt * 16 + lq;
            int col = wn * 64 + nt * 8 + lr * 2;
            float2 bb1 = *(const float2*)(b1 + col);
            float2 bb2 = *(const float2*)(b2 + col);
            float x0 = c1[mt][nt][0] + bb1.x;
            float x1 = c1[mt][nt][1] + bb1.y;
            float y0 = c2[mt][nt][0] + bb2.x;
            float y1 = c2[mt][nt][1] + bb2.y;
            float r0 = (x0 > 0.f ? x0 : 0.01f * x0) + (y0 > 0.f ? y0 : 0.01f * y0);
            float r1 = (x1 > 0.f ? x1 : 0.01f * x1) + (y1 > 0.f ? y1 : 0.01f * y1);
            *(float2*)(stage + row * STAGE_STRIDE + col) = make_float2(r0, r1);
            float x2 = c1[mt][nt][2] + bb1.x;
            float x3 = c1[mt][nt][3] + bb1.y;
            float y2 = c2[mt][nt][2] + bb2.x;
            float y3 = c2[mt][nt][3] + bb2.y;
            float r2 = (x2 > 0.f ? x2 : 0.01f * x2) + (y2 > 0.f ? y2 : 0.01f * y2);
            float r3 = (x3 > 0.f ? x3 : 0.01f * x3) + (y3 > 0.f ? y3 : 0.01f * y3);
            *(float2*)(stage + (row + 8) * STAGE_STRIDE + col) = make_float2(r2, r3);
        }
    }
    __syncthreads();

    for (int idx = tid; idx < FT * 32; idx += 256) {
        int m = idx >> 5, c4 = idx & 31;
        int mg = m0 + m;
        if (mg < NN) {
            float4 v = *(float4*)(stage + m * STAGE_STRIDE + c4 * 4);
            *((float4*)(out + (size_t)mg * DIM) + c4) = v;
        }
    }
}

// ---------------------------------------------------------------------------
extern "C" void kernel_launch(void* const* d_in, const int* in_sizes, int n_in,
                              void* d_out, int out_size) {
    const int*   erow = (const int*)d_in[0];
    const int*   ecol = (const int*)d_in[1];
    const float* eval = (const float*)d_in[2];
    const float* ego  = (const float*)d_in[3];
    const float* W1   = (const float*)d_in[4];
    const float* b1   = (const float*)d_in[5];
    const float* W2   = (const float*)d_in[6];
    const float* b2   = (const float*)d_in[7];
    float* out = (float*)d_out;

    cudaFuncSetAttribute(fused_mma_kernel,
                         cudaFuncAttributeMaxDynamicSharedMemorySize, SM_TOTAL);

    prephist_kernel<<<4096, 256>>>(ego, erow);             // launch 1
    scan_fused<<<NBLK, SCAN_B>>>();                        // launch 2
    scatter_kernel<<<4096, 256>>>(erow, ecol, eval);       // launch 3
    spmm_csr_kernel<<<(NN * 32 + 511) / 512, 512>>>();     // launch 4 (profiled)
    fused_mma_kernel<<<NTILE, 256, SM_TOTAL>>>(ego, W1, b1, W2, b2, out);
}